// round 10
// baseline (speedup 1.0000x reference)
#include <cuda_runtime.h>

#define NA  8400        // anchors / preds per batch
#define NC4 (NA/4)      // float4 columns = 2100
#define NG  2048        // bs*M flattened gts
#define BS  16
#define M   128
#define GTT 32          // gt tile per block (fully unrolled)
#define TPB 128
#define CB  ((NC4 + TPB - 1) / TPB)      // 17 column-blocks
#define DGB (CB * (NG / GTT))            // 17*64 = 1088
#define IOB (CB * (M / GTT) * BS)        // 17*4*16 = 1088

typedef unsigned long long u64;

__device__ __forceinline__ float frcp(float a) {
    float r; asm("rcp.approx.f32 %0, %1;" : "=f"(r) : "f"(a)); return r;
}
__device__ __forceinline__ float fsqrt_ap(float a) {
    float r; asm("sqrt.approx.f32 %0, %1;" : "=f"(r) : "f"(a)); return r;
}
__device__ __forceinline__ u64 pack2(float lo, float hi) {
    u64 r; asm("mov.b64 %0, {%1, %2};" : "=l"(r) : "f"(lo), "f"(hi)); return r;
}
__device__ __forceinline__ void unpack2(u64 v, float& lo, float& hi) {
    asm("mov.b64 {%0, %1}, %2;" : "=f"(lo), "=f"(hi) : "l"(v));
}
__device__ __forceinline__ u64 add2(u64 a, u64 b) {
    u64 r; asm("add.rn.f32x2 %0, %1, %2;" : "=l"(r) : "l"(a), "l"(b)); return r;
}
__device__ __forceinline__ u64 sub2(u64 a, u64 b) {
    u64 r; asm("sub.rn.f32x2 %0, %1, %2;" : "=l"(r) : "l"(a), "l"(b)); return r;
}
__device__ __forceinline__ u64 mul2(u64 a, u64 b) {
    u64 r; asm("mul.rn.f32x2 %0, %1, %2;" : "=l"(r) : "l"(a), "l"(b)); return r;
}
__device__ __forceinline__ u64 fma2(u64 a, u64 b, u64 c) {
    u64 r; asm("fma.rn.f32x2 %0, %1, %2, %3;" : "=l"(r) : "l"(a), "l"(b), "l"(c)); return r;
}

// smem per gt: [0]=box(x,y,z,w)  [1]=(gcx,gcx,gcy,gcy)  [2]=(tx,ty,area1,0)
__global__ __launch_bounds__(TPB)
void fused_kernel(const float4* __restrict__ gt,
                  const float4* __restrict__ pred,
                  const float4* __restrict__ anc,
                  float* __restrict__ dist,
                  float* __restrict__ ovlp,
                  float* __restrict__ giou)
{
    __shared__ float4 sg[GTT * 3];
    const int tid = threadIdx.x;
    int blk = blockIdx.x;

    if (blk < DGB) {
        // ================= distances + gious =================
        const int cb = blk % CB;
        const int g0 = (blk / CB) * GTT;
        if (tid < GTT) {
            const float4 g = gt[g0 + tid];
            sg[tid * 3 + 0] = g;
            const float gcx = 0.5f * (g.x + g.z);
            const float gcy = 0.5f * (g.y + g.w);
            sg[tid * 3 + 1] = make_float4(gcx, gcx, gcy, gcy);
            const float tx = g.z - g.x, ty = g.w - g.y;
            sg[tid * 3 + 2] = make_float4(tx, ty, tx * ty, 0.0f);
        }
        __syncthreads();

        const int c = cb * TPB + tid;
        if (c >= NC4) return;
        const int a = 4 * c;

        float Ax[4], Ay[4], Az[4], Aw[4], Aar[4];
        u64 Acx2[2], Acy2[2], Awh2[4];
        #pragma unroll
        for (int p = 0; p < 2; p++) {
            const float4 A0 = anc[a + 2 * p];
            const float4 A1 = anc[a + 2 * p + 1];
            Ax[2*p] = A0.x; Ay[2*p] = A0.y; Az[2*p] = A0.z; Aw[2*p] = A0.w;
            Ax[2*p+1] = A1.x; Ay[2*p+1] = A1.y; Az[2*p+1] = A1.z; Aw[2*p+1] = A1.w;
            Acx2[p] = pack2(0.5f * (A0.x + A0.z), 0.5f * (A1.x + A1.z));
            Acy2[p] = pack2(0.5f * (A0.y + A0.w), 0.5f * (A1.y + A1.w));
            float w0 = A0.z - A0.x, h0 = A0.w - A0.y;
            float w1 = A1.z - A1.x, h1 = A1.w - A1.y;
            Awh2[2*p]   = pack2(w0, h0);
            Awh2[2*p+1] = pack2(w1, h1);
            Aar[2*p]   = w0 * h0;
            Aar[2*p+1] = w1 * h1;
        }

        float* pd = dist + (long)g0 * NA + a;
        float* pg = giou + (long)g0 * NA + a;

        #pragma unroll
        for (int k = 0; k < GTT; k++) {
            const float4 gb = sg[k * 3 + 0];
            const ulonglong2 cc = *reinterpret_cast<const ulonglong2*>(&sg[k * 3 + 1]);
            const float4 tt = sg[k * 3 + 2];
            const u64 gwh2 = pack2(tt.x, tt.y);    // adjacent regs from LDS.128
            const float area1 = tt.z;

            // --- packed distances (lanes = anchor pair) ---
            float dv[4];
            #pragma unroll
            for (int p = 0; p < 2; p++) {
                u64 dx2 = sub2(cc.x, Acx2[p]);
                u64 dy2 = sub2(cc.y, Acy2[p]);
                u64 d2  = fma2(dx2, dx2, mul2(dy2, dy2));
                float lo, hi; unpack2(d2, lo, hi);
                dv[2*p]   = fsqrt_ap(lo);
                dv[2*p+1] = fsqrt_ap(hi);
            }

            // --- giou: scalar min/max, packed wh/enclosure, single rcp ---
            float gv[4];
            #pragma unroll
            for (int j = 0; j < 4; j++) {
                float mxx = fmaxf(gb.x, Ax[j]), mxy = fmaxf(gb.y, Ay[j]);
                float mnz = fminf(gb.z, Az[j]), mnw = fminf(gb.w, Aw[j]);
                u64 whr2 = sub2(pack2(mnz, mnw), pack2(mxx, mxy));
                float wraw, hraw; unpack2(whr2, wraw, hraw);
                float ov  = fmaxf(wraw, 0.0f) * fmaxf(hraw, 0.0f);
                float uni = (area1 + Aar[j]) - ov;            // >= 16 >> eps
                u64 ewh2 = sub2(add2(gwh2, Awh2[j]), whr2);
                float ew, eh; unpack2(ewh2, ew, eh);
                float enc = ew * eh;
                // giou = (ov*enc + uni^2) / (uni*enc) - 1
                float num = fmaf(ov, enc, uni * uni);
                gv[j] = fmaf(num, frcp(uni * enc), -1.0f);
            }
            __stcs((float4*)(pd + k * NA), make_float4(dv[0], dv[1], dv[2], dv[3]));
            __stcs((float4*)(pg + k * NA), make_float4(gv[0], gv[1], gv[2], gv[3]));
        }
    } else {
        // ================= gt-vs-pred IoU =================
        blk -= DGB;
        const int cb = blk % CB;
        const int r  = blk / CB;
        const int m0 = (r & 3) * GTT;     // M/GTT == 4
        const int b  = r >> 2;

        if (tid < GTT) {
            const float4 g = gt[b * M + m0 + tid];
            sg[tid * 3 + 0] = g;
            sg[tid * 3 + 2] = make_float4(0.f, 0.f, (g.z - g.x) * (g.w - g.y), 0.f);
        }
        __syncthreads();

        const int c = cb * TPB + tid;
        if (c >= NC4) return;
        const int a = 4 * c;

        float Px[4], Py[4], Pz[4], Pw[4], Par[4];
        #pragma unroll
        for (int j = 0; j < 4; j++) {
            const float4 P = pred[b * NA + a + j];
            Px[j] = P.x; Py[j] = P.y; Pz[j] = P.z; Pw[j] = P.w;
            Par[j] = (P.z - P.x) * (P.w - P.y) + 1e-9f;
        }

        float* po = ovlp + ((long)b * M + m0) * NA + a;

        #pragma unroll
        for (int k = 0; k < GTT; k++) {
            const float4 gb = sg[k * 3 + 0];
            const float area1 = sg[k * 3 + 2].z;

            float rv[4];
            #pragma unroll
            for (int j = 0; j < 4; j++) {
                float w = fmaxf(fminf(gb.z, Pz[j]) - fmaxf(gb.x, Px[j]), 0.0f);
                float h = fmaxf(fminf(gb.w, Pw[j]) - fmaxf(gb.y, Py[j]), 0.0f);
                float ov = w * h;
                rv[j] = ov * frcp((area1 + Par[j]) - ov);
            }
            __stcs((float4*)(po + k * NA), make_float4(rv[0], rv[1], rv[2], rv[3]));
        }
    }
}

extern "C" void kernel_launch(void* const* d_in, const int* in_sizes, int n_in,
                              void* d_out, int out_size)
{
    const float4* gt   = (const float4*)d_in[0];
    const float4* pred = (const float4*)d_in[1];
    const float4* anc  = (const float4*)d_in[2];

    float* dist = (float*)d_out;
    float* ovlp = dist + (long)NG * NA;
    float* giou = ovlp + (long)BS * M * NA;

    fused_kernel<<<DGB + IOB, TPB>>>(gt, pred, anc, dist, ovlp, giou);
}

// round 11
// speedup vs baseline: 1.1214x; 1.1214x over previous
#include <cuda_runtime.h>

#define NA  8400        // anchors / preds per batch
#define NC4 (NA/4)      // float4 columns = 2100
#define NG  2048        // bs*M flattened gts
#define BS  16
#define M   128
#define GTT 16          // gt tile per block (fully unrolled)
#define TPB 128
#define CB  ((NC4 + TPB - 1) / TPB)      // 17 column-blocks
#define DGB (CB * (NG / GTT))            // 17*128 = 2176
#define IOB (CB * (M / GTT) * BS)        // 17*8*16 = 2176

typedef unsigned long long u64;

__device__ __forceinline__ float frcp(float a) {
    float r; asm("rcp.approx.f32 %0, %1;" : "=f"(r) : "f"(a)); return r;
}
__device__ __forceinline__ float fsqrt_ap(float a) {
    float r; asm("sqrt.approx.f32 %0, %1;" : "=f"(r) : "f"(a)); return r;
}
__device__ __forceinline__ u64 pack2(float lo, float hi) {
    u64 r; asm("mov.b64 %0, {%1, %2};" : "=l"(r) : "f"(lo), "f"(hi)); return r;
}
__device__ __forceinline__ void unpack2(u64 v, float& lo, float& hi) {
    asm("mov.b64 {%0, %1}, %2;" : "=f"(lo), "=f"(hi) : "l"(v));
}
__device__ __forceinline__ u64 add2(u64 a, u64 b) {
    u64 r; asm("add.rn.f32x2 %0, %1, %2;" : "=l"(r) : "l"(a), "l"(b)); return r;
}
__device__ __forceinline__ u64 sub2(u64 a, u64 b) {
    u64 r; asm("sub.rn.f32x2 %0, %1, %2;" : "=l"(r) : "l"(a), "l"(b)); return r;
}
__device__ __forceinline__ u64 mul2(u64 a, u64 b) {
    u64 r; asm("mul.rn.f32x2 %0, %1, %2;" : "=l"(r) : "l"(a), "l"(b)); return r;
}
__device__ __forceinline__ u64 fma2(u64 a, u64 b, u64 c) {
    u64 r; asm("fma.rn.f32x2 %0, %1, %2, %3;" : "=l"(r) : "l"(a), "l"(b), "l"(c)); return r;
}

// smem per gt: [0]=box(x,y,z,w)  [1]=(gcx,gcx,gcy,gcy)  [2]=(tx,ty,area1,0)
__global__ __launch_bounds__(TPB)
void fused_kernel(const float4* __restrict__ gt,
                  const float4* __restrict__ pred,
                  const float4* __restrict__ anc,
                  float* __restrict__ dist,
                  float* __restrict__ ovlp,
                  float* __restrict__ giou)
{
    __shared__ float4 sg[GTT * 3];
    const int tid = threadIdx.x;
    int blk = blockIdx.x;

    if (blk < DGB) {
        // ================= distances + gious =================
        const int cb = blk % CB;
        const int g0 = (blk / CB) * GTT;
        if (tid < GTT) {
            const float4 g = gt[g0 + tid];
            sg[tid * 3 + 0] = g;
            const float gcx = 0.5f * (g.x + g.z);
            const float gcy = 0.5f * (g.y + g.w);
            sg[tid * 3 + 1] = make_float4(gcx, gcx, gcy, gcy);
            const float tx = g.z - g.x, ty = g.w - g.y;
            sg[tid * 3 + 2] = make_float4(tx, ty, tx * ty, 0.0f);
        }
        __syncthreads();

        const int c = cb * TPB + tid;
        if (c >= NC4) return;
        const int a = 4 * c;

        float Ax[4], Ay[4], Az[4], Aw[4], Aar[4];
        u64 Acx2[2], Acy2[2], Awh2[4];
        #pragma unroll
        for (int p = 0; p < 2; p++) {
            const float4 A0 = anc[a + 2 * p];
            const float4 A1 = anc[a + 2 * p + 1];
            Ax[2*p] = A0.x; Ay[2*p] = A0.y; Az[2*p] = A0.z; Aw[2*p] = A0.w;
            Ax[2*p+1] = A1.x; Ay[2*p+1] = A1.y; Az[2*p+1] = A1.z; Aw[2*p+1] = A1.w;
            Acx2[p] = pack2(0.5f * (A0.x + A0.z), 0.5f * (A1.x + A1.z));
            Acy2[p] = pack2(0.5f * (A0.y + A0.w), 0.5f * (A1.y + A1.w));
            float w0 = A0.z - A0.x, h0 = A0.w - A0.y;
            float w1 = A1.z - A1.x, h1 = A1.w - A1.y;
            Awh2[2*p]   = pack2(w0, h0);
            Awh2[2*p+1] = pack2(w1, h1);
            Aar[2*p]   = w0 * h0;
            Aar[2*p+1] = w1 * h1;
        }

        float* pd = dist + (long)g0 * NA + a;
        float* pg = giou + (long)g0 * NA + a;

        #pragma unroll
        for (int k = 0; k < GTT; k++) {
            const float4 gb = sg[k * 3 + 0];
            const ulonglong2 cc = *reinterpret_cast<const ulonglong2*>(&sg[k * 3 + 1]);
            const float4 tt = sg[k * 3 + 2];
            const u64 gwh2 = pack2(tt.x, tt.y);    // adjacent regs from LDS.128
            const float area1 = tt.z;

            // --- packed distances (lanes = anchor pair) ---
            float dv[4];
            #pragma unroll
            for (int p = 0; p < 2; p++) {
                u64 dx2 = sub2(cc.x, Acx2[p]);
                u64 dy2 = sub2(cc.y, Acy2[p]);
                u64 d2  = fma2(dx2, dx2, mul2(dy2, dy2));
                float lo, hi; unpack2(d2, lo, hi);
                dv[2*p]   = fsqrt_ap(lo);
                dv[2*p+1] = fsqrt_ap(hi);
            }

            // --- giou: scalar min/max, packed wh/enclosure, single rcp ---
            float gv[4];
            #pragma unroll
            for (int j = 0; j < 4; j++) {
                float mxx = fmaxf(gb.x, Ax[j]), mxy = fmaxf(gb.y, Ay[j]);
                float mnz = fminf(gb.z, Az[j]), mnw = fminf(gb.w, Aw[j]);
                u64 whr2 = sub2(pack2(mnz, mnw), pack2(mxx, mxy));
                float wraw, hraw; unpack2(whr2, wraw, hraw);
                float ov  = fmaxf(wraw, 0.0f) * fmaxf(hraw, 0.0f);
                float uni = (area1 + Aar[j]) - ov;            // >= 16 >> eps
                u64 ewh2 = sub2(add2(gwh2, Awh2[j]), whr2);
                float ew, eh; unpack2(ewh2, ew, eh);
                float enc = ew * eh;
                // giou = (ov*enc + uni^2) / (uni*enc) - 1
                float num = fmaf(ov, enc, uni * uni);
                gv[j] = fmaf(num, frcp(uni * enc), -1.0f);
            }
            __stcs((float4*)(pd + k * NA), make_float4(dv[0], dv[1], dv[2], dv[3]));
            __stcs((float4*)(pg + k * NA), make_float4(gv[0], gv[1], gv[2], gv[3]));
        }
    } else {
        // ================= gt-vs-pred IoU =================
        blk -= DGB;
        const int cb = blk % CB;
        const int r  = blk / CB;
        const int m0 = (r & 7) * GTT;     // M/GTT == 8
        const int b  = r >> 3;

        if (tid < GTT) {
            const float4 g = gt[b * M + m0 + tid];
            sg[tid * 3 + 0] = g;
            sg[tid * 3 + 2] = make_float4(0.f, 0.f, (g.z - g.x) * (g.w - g.y), 0.f);
        }
        __syncthreads();

        const int c = cb * TPB + tid;
        if (c >= NC4) return;
        const int a = 4 * c;

        float Px[4], Py[4], Pz[4], Pw[4], Par[4];
        #pragma unroll
        for (int j = 0; j < 4; j++) {
            const float4 P = pred[b * NA + a + j];
            Px[j] = P.x; Py[j] = P.y; Pz[j] = P.z; Pw[j] = P.w;
            Par[j] = (P.z - P.x) * (P.w - P.y) + 1e-9f;
        }

        float* po = ovlp + ((long)b * M + m0) * NA + a;

        #pragma unroll
        for (int k = 0; k < GTT; k++) {
            const float4 gb = sg[k * 3 + 0];
            const float area1 = sg[k * 3 + 2].z;

            float rv[4];
            #pragma unroll
            for (int j = 0; j < 4; j++) {
                float w = fmaxf(fminf(gb.z, Pz[j]) - fmaxf(gb.x, Px[j]), 0.0f);
                float h = fmaxf(fminf(gb.w, Pw[j]) - fmaxf(gb.y, Py[j]), 0.0f);
                float ov = w * h;
                rv[j] = ov * frcp((area1 + Par[j]) - ov);
            }
            __stcs((float4*)(po + k * NA), make_float4(rv[0], rv[1], rv[2], rv[3]));
        }
    }
}

extern "C" void kernel_launch(void* const* d_in, const int* in_sizes, int n_in,
                              void* d_out, int out_size)
{
    const float4* gt   = (const float4*)d_in[0];
    const float4* pred = (const float4*)d_in[1];
    const float4* anc  = (const float4*)d_in[2];

    float* dist = (float*)d_out;
    float* ovlp = dist + (long)NG * NA;
    float* giou = ovlp + (long)BS * M * NA;

    fused_kernel<<<DGB + IOB, TPB>>>(gt, pred, anc, dist, ovlp, giou);
}

// round 12
// speedup vs baseline: 1.1687x; 1.0422x over previous
#include <cuda_runtime.h>

#define NA  8400        // anchors / preds per batch
#define NC4 (NA/4)      // float4 columns = 2100
#define NG  2048        // bs*M flattened gts
#define BS  16
#define M   128
#define GTT 16          // gt tile per block (fully unrolled)
#define TPB 128
#define CB  ((NC4 + TPB - 1) / TPB)      // 17 column-blocks
#define DGB (CB * (NG / GTT))            // 17*128 = 2176
#define IOB (CB * (M / GTT) * BS)        // 17*8*16 = 2176

typedef unsigned long long u64;

__device__ __forceinline__ float frcp(float a) {
    float r; asm("rcp.approx.f32 %0, %1;" : "=f"(r) : "f"(a)); return r;
}
__device__ __forceinline__ float fsqrt_ap(float a) {
    float r; asm("sqrt.approx.f32 %0, %1;" : "=f"(r) : "f"(a)); return r;
}
__device__ __forceinline__ u64 pack2(float lo, float hi) {
    u64 r; asm("mov.b64 %0, {%1, %2};" : "=l"(r) : "f"(lo), "f"(hi)); return r;
}
__device__ __forceinline__ void unpack2(u64 v, float& lo, float& hi) {
    asm("mov.b64 {%0, %1}, %2;" : "=f"(lo), "=f"(hi) : "l"(v));
}
__device__ __forceinline__ u64 add2(u64 a, u64 b) {
    u64 r; asm("add.rn.f32x2 %0, %1, %2;" : "=l"(r) : "l"(a), "l"(b)); return r;
}
__device__ __forceinline__ u64 sub2(u64 a, u64 b) {
    u64 r; asm("sub.rn.f32x2 %0, %1, %2;" : "=l"(r) : "l"(a), "l"(b)); return r;
}
__device__ __forceinline__ u64 mul2(u64 a, u64 b) {
    u64 r; asm("mul.rn.f32x2 %0, %1, %2;" : "=l"(r) : "l"(a), "l"(b)); return r;
}
__device__ __forceinline__ u64 fma2(u64 a, u64 b, u64 c) {
    u64 r; asm("fma.rn.f32x2 %0, %1, %2, %3;" : "=l"(r) : "l"(a), "l"(b), "l"(c)); return r;
}

// smem per gt: [0]=box(x,y,z,w)  [1]=(gcx,gcx,gcy,gcy)  [2]=(tx,ty,area1,0)
__global__ __launch_bounds__(TPB)
void fused_kernel(const float4* __restrict__ gt,
                  const float4* __restrict__ pred,
                  const float4* __restrict__ anc,
                  float* __restrict__ dist,
                  float* __restrict__ ovlp,
                  float* __restrict__ giou)
{
    __shared__ float4 sg[GTT * 3];
    const int tid = threadIdx.x;
    int blk = blockIdx.x;

    if (blk < DGB) {
        // ================= distances + gious =================
        const int cb = blk % CB;
        const int g0 = (blk / CB) * GTT;
        if (tid < GTT) {
            const float4 g = gt[g0 + tid];
            sg[tid * 3 + 0] = g;
            const float gcx = 0.5f * (g.x + g.z);
            const float gcy = 0.5f * (g.y + g.w);
            sg[tid * 3 + 1] = make_float4(gcx, gcx, gcy, gcy);
            const float tx = g.z - g.x, ty = g.w - g.y;
            sg[tid * 3 + 2] = make_float4(tx, ty, tx * ty, 0.0f);
        }
        __syncthreads();

        const int c = cb * TPB + tid;
        if (c >= NC4) return;
        const int a = 4 * c;

        float Ax[4], Ay[4], Az[4], Aw[4], Aar[4];
        u64 Acx2[2], Acy2[2], Awh2[4];
        #pragma unroll
        for (int p = 0; p < 2; p++) {
            const float4 A0 = anc[a + 2 * p];
            const float4 A1 = anc[a + 2 * p + 1];
            Ax[2*p] = A0.x; Ay[2*p] = A0.y; Az[2*p] = A0.z; Aw[2*p] = A0.w;
            Ax[2*p+1] = A1.x; Ay[2*p+1] = A1.y; Az[2*p+1] = A1.z; Aw[2*p+1] = A1.w;
            Acx2[p] = pack2(0.5f * (A0.x + A0.z), 0.5f * (A1.x + A1.z));
            Acy2[p] = pack2(0.5f * (A0.y + A0.w), 0.5f * (A1.y + A1.w));
            float w0 = A0.z - A0.x, h0 = A0.w - A0.y;
            float w1 = A1.z - A1.x, h1 = A1.w - A1.y;
            Awh2[2*p]   = pack2(w0, h0);
            Awh2[2*p+1] = pack2(w1, h1);
            Aar[2*p]   = w0 * h0;
            Aar[2*p+1] = w1 * h1;
        }

        float* pd = dist + (long)g0 * NA + a;
        float* pg = giou + (long)g0 * NA + a;

        #pragma unroll
        for (int k = 0; k < GTT; k++) {
            const float4 gb = sg[k * 3 + 0];
            const ulonglong2 cc = *reinterpret_cast<const ulonglong2*>(&sg[k * 3 + 1]);
            const float4 tt = sg[k * 3 + 2];
            const u64 gwh2 = pack2(tt.x, tt.y);
            const float area1 = tt.z;

            // --- packed distances (lanes = anchor pair) ---
            float dv[4];
            #pragma unroll
            for (int p = 0; p < 2; p++) {
                u64 dx2 = sub2(cc.x, Acx2[p]);
                u64 dy2 = sub2(cc.y, Acy2[p]);
                u64 d2  = fma2(dx2, dx2, mul2(dy2, dy2));
                float lo, hi; unpack2(d2, lo, hi);
                dv[2*p]   = fsqrt_ap(lo);
                dv[2*p+1] = fsqrt_ap(hi);
            }

            // --- giou: scalar min/max, packed wh/enclosure, PAIRED rcp ---
            float gv[4];
            #pragma unroll
            for (int p = 0; p < 2; p++) {
                float num[2], den[2];
                #pragma unroll
                for (int q = 0; q < 2; q++) {
                    const int j = 2 * p + q;
                    float mxx = fmaxf(gb.x, Ax[j]), mxy = fmaxf(gb.y, Ay[j]);
                    float mnz = fminf(gb.z, Az[j]), mnw = fminf(gb.w, Aw[j]);
                    u64 whr2 = sub2(pack2(mnz, mnw), pack2(mxx, mxy));
                    float wraw, hraw; unpack2(whr2, wraw, hraw);
                    float ov  = fmaxf(wraw, 0.0f) * fmaxf(hraw, 0.0f);
                    float uni = (area1 + Aar[j]) - ov;        // >= 16 >> eps
                    u64 ewh2 = sub2(add2(gwh2, Awh2[j]), whr2);
                    float ew, eh; unpack2(ewh2, ew, eh);
                    float enc = ew * eh;
                    num[q] = fmaf(ov, enc, uni * uni);        // ov*enc + uni^2
                    den[q] = uni * enc;                       // [6.5e4, 6e10]
                }
                // one rcp for two denominators: r = 1/(d0*d1)
                float r = frcp(den[0] * den[1]);
                gv[2*p]   = fmaf(num[0], r * den[1], -1.0f);
                gv[2*p+1] = fmaf(num[1], r * den[0], -1.0f);
            }
            __stcs((float4*)(pd + k * NA), make_float4(dv[0], dv[1], dv[2], dv[3]));
            __stcs((float4*)(pg + k * NA), make_float4(gv[0], gv[1], gv[2], gv[3]));
        }
    } else {
        // ================= gt-vs-pred IoU =================
        blk -= DGB;
        const int cb = blk % CB;
        const int r  = blk / CB;
        const int m0 = (r & 7) * GTT;     // M/GTT == 8
        const int b  = r >> 3;

        if (tid < GTT) {
            const float4 g = gt[b * M + m0 + tid];
            sg[tid * 3 + 0] = g;
            sg[tid * 3 + 2] = make_float4(0.f, 0.f, (g.z - g.x) * (g.w - g.y), 0.f);
        }
        __syncthreads();

        const int c = cb * TPB + tid;
        if (c >= NC4) return;
        const int a = 4 * c;

        float Px[4], Py[4], Pz[4], Pw[4], Par[4];
        #pragma unroll
        for (int j = 0; j < 4; j++) {
            const float4 P = pred[b * NA + a + j];
            Px[j] = P.x; Py[j] = P.y; Pz[j] = P.z; Pw[j] = P.w;
            Par[j] = (P.z - P.x) * (P.w - P.y) + 1e-9f;
        }

        float* po = ovlp + ((long)b * M + m0) * NA + a;

        #pragma unroll
        for (int k = 0; k < GTT; k++) {
            const float4 gb = sg[k * 3 + 0];
            const float area1 = sg[k * 3 + 2].z;

            float rv[4];
            #pragma unroll
            for (int p = 0; p < 2; p++) {
                float ov[2], den[2];
                #pragma unroll
                for (int q = 0; q < 2; q++) {
                    const int j = 2 * p + q;
                    float w = fmaxf(fminf(gb.z, Pz[j]) - fmaxf(gb.x, Px[j]), 0.0f);
                    float h = fmaxf(fminf(gb.w, Pw[j]) - fmaxf(gb.y, Py[j]), 0.0f);
                    ov[q]  = w * h;
                    den[q] = (area1 + Par[j]) - ov[q];        // >= ~16
                }
                float r = frcp(den[0] * den[1]);
                rv[2*p]   = ov[0] * (r * den[1]);
                rv[2*p+1] = ov[1] * (r * den[0]);
            }
            __stcs((float4*)(po + k * NA), make_float4(rv[0], rv[1], rv[2], rv[3]));
        }
    }
}

extern "C" void kernel_launch(void* const* d_in, const int* in_sizes, int n_in,
                              void* d_out, int out_size)
{
    const float4* gt   = (const float4*)d_in[0];
    const float4* pred = (const float4*)d_in[1];
    const float4* anc  = (const float4*)d_in[2];

    float* dist = (float*)d_out;
    float* ovlp = dist + (long)NG * NA;
    float* giou = ovlp + (long)BS * M * NA;

    fused_kernel<<<DGB + IOB, TPB>>>(gt, pred, anc, dist, ovlp, giou);
}